// round 16
// baseline (speedup 1.0000x reference)
#include <cuda_runtime.h>
#include <cuda_fp16.h>
#include <math.h>
#include <stdint.h>

// ---------------------------------------------------------------------------
// Problem constants
// ---------------------------------------------------------------------------
#define B_ 4
#define T_ 2048
#define H_ 1024
#define DFF_ 4096
#define M_ (B_ * T_)      // 8192 tokens
#define HALF_ (H_ / 2)    // 512
#define ACT_TAU 0.99f
#define TARGET_DEPTH 2.5f
#define BUDGET_WEIGHT 0.01f
#define RW1_ROWS 1025

// ---------------------------------------------------------------------------
// Device scratch (no allocations allowed)
// ---------------------------------------------------------------------------
__device__ __align__(16) __half g_W1h[(size_t)H_ * DFF_];
__device__ __align__(16) __half g_W2h[(size_t)DFF_ * H_];
__device__ __align__(16) __half g_R1h[(size_t)3 * RW1_ROWS * HALF_];
__device__ __align__(16) __half g_xh[(size_t)M_ * H_];
__device__ __align__(16) __half g_hh[(size_t)M_ * DFF_];
__device__ float g_x[(size_t)M_ * H_];
__device__ float g_rh[(size_t)M_ * HALF_];
__device__ float g_w[M_];
__device__ float g_cum[M_];
__device__ float g_still[M_];
__device__ float g_wsum[M_];

// ---------------------------------------------------------------------------
// Helpers
// ---------------------------------------------------------------------------
__device__ __forceinline__ uint32_t smem_u32(const void* p) {
    uint32_t a;
    asm("{ .reg .u64 t; cvta.to.shared.u64 t, %1; cvt.u32.u64 %0, t; }"
        : "=r"(a) : "l"(p));
    return a;
}

__device__ __forceinline__ float gelu_exact(float v) {
    return 0.5f * v * (1.0f + erff(v * 0.70710678118654752440f));
}

__device__ __forceinline__ void cpa16(uint32_t dst, const void* src) {
    asm volatile("cp.async.cg.shared.global [%0], [%1], 16;" :: "r"(dst), "l"(src));
}
__device__ __forceinline__ void cpa_commit() {
    asm volatile("cp.async.commit_group;" ::: "memory");
}
template <int N>
__device__ __forceinline__ void cpa_wait() {
    asm volatile("cp.async.wait_group %0;" :: "n"(N) : "memory");
}

__device__ __forceinline__ void ldsm_x4(uint32_t* r, uint32_t addr) {
    asm volatile("ldmatrix.sync.aligned.m8n8.x4.shared.b16 {%0,%1,%2,%3}, [%4];"
                 : "=r"(r[0]), "=r"(r[1]), "=r"(r[2]), "=r"(r[3]) : "r"(addr));
}
__device__ __forceinline__ void ldsm_x4t(uint32_t* r, uint32_t addr) {
    asm volatile("ldmatrix.sync.aligned.m8n8.x4.trans.shared.b16 {%0,%1,%2,%3}, [%4];"
                 : "=r"(r[0]), "=r"(r[1]), "=r"(r[2]), "=r"(r[3]) : "r"(addr));
}

// mma m16n8k16 fp16 -> fp32 accum
__device__ __forceinline__ void mma_f16(float* c, const uint32_t* a,
                                        uint32_t b0, uint32_t b1) {
    asm volatile(
        "mma.sync.aligned.m16n8k16.row.col.f32.f16.f16.f32 "
        "{%0,%1,%2,%3}, {%4,%5,%6,%7}, {%8,%9}, {%0,%1,%2,%3};"
        : "+f"(c[0]), "+f"(c[1]), "+f"(c[2]), "+f"(c[3])
        : "r"(a[0]), "r"(a[1]), "r"(a[2]), "r"(a[3]), "r"(b0), "r"(b1));
}

// ---------------------------------------------------------------------------
// fp32 -> fp16 convert
// ---------------------------------------------------------------------------
__global__ void split_hi_kernel(const float* __restrict__ src,
                                __half* __restrict__ hi, int n4)
{
    int i = blockIdx.x * 256 + threadIdx.x;
    if (i >= n4) return;
    float4 v = ((const float4*)src)[i];
    ((__half2*)hi)[i * 2 + 0] = __halves2half2(__float2half_rn(v.x), __float2half_rn(v.y));
    ((__half2*)hi)[i * 2 + 1] = __halves2half2(__float2half_rn(v.z), __float2half_rn(v.w));
}

// ---------------------------------------------------------------------------
// Tile config A: CTA 64x128, 128 threads (2x2 warps of 32x64), 5 CTAs/SM.
// ---------------------------------------------------------------------------
#define TBM 64
#define TBN 128
#define TBK 32
#define NTHR 128
#define AST 80       // A smem row stride bytes (32 fp16 = 64B + 16 pad)
#define BST 272      // B smem row stride bytes (128 fp16 = 256B + 16 pad)
#define A_BYTES (TBM * AST)                 // 5120
#define B_BYTES (32 * BST)                  // 8704
#define ST_AH 0
#define ST_BH A_BYTES
#define STAGE_BYTES (A_BYTES + B_BYTES)     // 13824
#define SMEM_BYTES (2 * STAGE_BYTES)        // 27648

// Tile config B (GEMM2): CTA 64x64, 128 threads (2x2 warps of 32x32), 6 CTAs/SM.
#define BST64 144    // 64 fp16 = 128B + 16 pad
#define B64_BYTES (32 * BST64)              // 4608
#define STAGE64_BYTES (A_BYTES + B64_BYTES) // 9728
#define SMEM64_BYTES (2 * STAGE64_BYTES)    // 19456

// Mainloop (TBN=128): acc[2][8][4] = A_h[M,K] * W_h[K,N].
#define GEMM_MAINLOOP(Ah_, Wh_, ldw_, K_)                                        \
    const int NC = (K_) / TBK;                                                   \
    auto load_chunk = [&](int c) {                                               \
        const uint32_t st = sm + (uint32_t)((c & 1) * STAGE_BYTES);              \
        const int k0 = c * TBK;                                                  \
        _Pragma("unroll")                                                        \
        for (int s = 0; s < 2; s++) {                                            \
            int gidx = tid + NTHR * s;       /* 0..255 A granules */             \
            int r = gidx >> 2, o = gidx & 3;                                     \
            size_t go = (size_t)(row_base + r) * (K_) + k0 + o * 8;              \
            cpa16(st + ST_AH + (uint32_t)(r * AST + o * 16), (Ah_) + go);        \
        }                                                                        \
        _Pragma("unroll")                                                        \
        for (int s = 0; s < 4; s++) {                                            \
            int gidx = tid + NTHR * s;       /* 0..511 B granules */             \
            int r = gidx >> 4, o = gidx & 15;                                    \
            size_t go = (size_t)(k0 + r) * (ldw_) + col_base + o * 8;            \
            cpa16(st + ST_BH + (uint32_t)(r * BST + o * 16), (Wh_) + go);        \
        }                                                                        \
        cpa_commit();                                                            \
    };                                                                           \
    load_chunk(0);                                                               \
    for (int c = 0; c < NC; c++) {                                               \
        if (c + 1 < NC) { load_chunk(c + 1); cpa_wait<1>(); }                    \
        else            { cpa_wait<0>(); }                                       \
        __syncthreads();                                                         \
        const uint32_t st = sm + (uint32_t)((c & 1) * STAGE_BYTES);              \
        _Pragma("unroll")                                                        \
        for (int ks = 0; ks < 2; ks++) {                                         \
            uint32_t ah[2][4], bh[4][4];                                         \
            _Pragma("unroll")                                                    \
            for (int mi = 0; mi < 2; mi++)                                       \
                ldsm_x4(ah[mi], st + ST_AH + a_lane +                            \
                                (uint32_t)(mi * 16 * AST + ks * 32));            \
            _Pragma("unroll")                                                    \
            for (int ni = 0; ni < 4; ni++)                                       \
                ldsm_x4t(bh[ni], st + ST_BH + b_lane +                           \
                                 (uint32_t)(ks * 16 * BST + ni * 32));           \
            _Pragma("unroll")                                                    \
            for (int ni = 0; ni < 4; ni++)                                       \
                _Pragma("unroll")                                                \
                for (int mi = 0; mi < 2; mi++) {                                 \
                    mma_f16(acc[mi][ni * 2 + 0], ah[mi], bh[ni][0], bh[ni][1]);  \
                    mma_f16(acc[mi][ni * 2 + 1], ah[mi], bh[ni][2], bh[ni][3]);  \
                }                                                                \
        }                                                                        \
        __syncthreads();                                                         \
    }

// ---------------------------------------------------------------------------
// Fused body-GEMM1 + router-GEMM kernel (TBN=128 config).
//   bx < 32 : h-tile  = gelu(x*W1 + bb1)      -> hh (fp16, ld 4096)
//   bx >= 32: rh-tile = gelu(x*Rw1_i + Rb1_i) -> rh (fp32, ld 512)
// ---------------------------------------------------------------------------
__global__ __launch_bounds__(NTHR, 5)
void g1_router(const __half* __restrict__ Ah,
               const __half* __restrict__ W1, const float* __restrict__ b1,
               __half* __restrict__ Chh,
               const __half* __restrict__ Wr, const float* __restrict__ br,
               float* __restrict__ Crh)
{
    extern __shared__ char smp[];
    const uint32_t sm = smem_u32(smp);

    const int tid = threadIdx.x;
    const int lane = tid & 31;
    const int warp = tid >> 5;
    const int warp_m = warp & 1;          // 2 warps along M -> 32 rows each
    const int warp_n = warp >> 1;         // 2 warps along N -> 64 cols each
    const int row_base = blockIdx.y * TBM;

    const bool is_r = (blockIdx.x >= 32);
    const int col_base = (is_r ? (blockIdx.x - 32) : blockIdx.x) * TBN;
    const __half* Wh = is_r ? Wr : W1;
    const float* bias = is_r ? br : b1;
    const int ldw = is_r ? HALF_ : DFF_;

    float acc[2][8][4];
#pragma unroll
    for (int i = 0; i < 2; i++)
#pragma unroll
        for (int j = 0; j < 8; j++)
#pragma unroll
            for (int k = 0; k < 4; k++) acc[i][j][k] = 0.0f;

    const uint32_t a_lane = (uint32_t)((warp_m * 32 + (lane & 15)) * AST +
                                       (lane >> 4) * 16);
    const uint32_t b_lane = (uint32_t)((((lane >> 3) & 1) * 8 + (lane & 7)) * BST +
                                       (warp_n * 64 + (lane >> 4) * 8) * 2);

    GEMM_MAINLOOP(Ah, Wh, ldw, H_)

    const int g = lane >> 2;
    const int tg = lane & 3;
    float bv0[8], bv1[8];
#pragma unroll
    for (int nj = 0; nj < 8; nj++) {
        const int gcol = col_base + warp_n * 64 + nj * 8 + tg * 2;
        bv0[nj] = bias[gcol];
        bv1[nj] = bias[gcol + 1];
    }

#pragma unroll
    for (int mi = 0; mi < 2; mi++) {
        const int r0 = row_base + warp_m * 32 + mi * 16 + g;
        const int r1 = r0 + 8;
#pragma unroll
        for (int nj = 0; nj < 8; nj++) {
            const int gcol = col_base + warp_n * 64 + nj * 8 + tg * 2;
            float v00 = gelu_exact(acc[mi][nj][0] + bv0[nj]);
            float v01 = gelu_exact(acc[mi][nj][1] + bv1[nj]);
            float v10 = gelu_exact(acc[mi][nj][2] + bv0[nj]);
            float v11 = gelu_exact(acc[mi][nj][3] + bv1[nj]);
            if (is_r) {
                *(float2*)&Crh[(size_t)r0 * HALF_ + gcol] = make_float2(v00, v01);
                *(float2*)&Crh[(size_t)r1 * HALF_ + gcol] = make_float2(v10, v11);
            } else {
                *(__half2*)&Chh[(size_t)r0 * DFF_ + gcol] =
                    __halves2half2(__float2half_rn(v00), __float2half_rn(v01));
                *(__half2*)&Chh[(size_t)r1 * DFF_ + gcol] =
                    __halves2half2(__float2half_rn(v10), __float2half_rn(v11));
            }
        }
    }
}

// ---------------------------------------------------------------------------
// GEMM2 kernel: CTA 64x64, warp tile 32x32, 6 CTAs/SM.
// EPI: 0=bias, 2=bias+ACT mix.  WF: write fp32 Cf.  WH: write fp16 Chh.
// Per-output K-order identical to the TBN=128 version -> bit-identical.
// ---------------------------------------------------------------------------
template <int EPI, int WF, int WH>
__global__ __launch_bounds__(NTHR, 6)
void tgemm64(const __half* __restrict__ Ah, const __half* __restrict__ Wh,
             const float* __restrict__ bias, float* __restrict__ Cf,
             __half* __restrict__ Chh,
             int M, int N, int K,
             const float* __restrict__ wmix, const float* __restrict__ xold)
{
    extern __shared__ char smp[];
    const uint32_t sm = smem_u32(smp);

    const int tid = threadIdx.x;
    const int lane = tid & 31;
    const int warp = tid >> 5;
    const int warp_m = warp & 1;          // 2 warps along M -> 32 rows each
    const int warp_n = warp >> 1;         // 2 warps along N -> 32 cols each
    const int row_base = blockIdx.y * TBM;
    const int col_base = blockIdx.x * 64;

    float acc[2][4][4];
#pragma unroll
    for (int i = 0; i < 2; i++)
#pragma unroll
        for (int j = 0; j < 4; j++)
#pragma unroll
            for (int k = 0; k < 4; k++) acc[i][j][k] = 0.0f;

    const uint32_t a_lane = (uint32_t)((warp_m * 32 + (lane & 15)) * AST +
                                       (lane >> 4) * 16);
    const uint32_t b_lane = (uint32_t)((((lane >> 3) & 1) * 8 + (lane & 7)) * BST64 +
                                       (warp_n * 32 + (lane >> 4) * 8) * 2);

    const int NC = K / TBK;
    auto load_chunk = [&](int c) {
        const uint32_t st = sm + (uint32_t)((c & 1) * STAGE64_BYTES);
        const int k0 = c * TBK;
#pragma unroll
        for (int s = 0; s < 2; s++) {
            int gidx = tid + NTHR * s;       // 0..255 A granules
            int r = gidx >> 2, o = gidx & 3;
            size_t go = (size_t)(row_base + r) * K + k0 + o * 8;
            cpa16(st + ST_AH + (uint32_t)(r * AST + o * 16), Ah + go);
        }
#pragma unroll
        for (int s = 0; s < 2; s++) {
            int gidx = tid + NTHR * s;       // 0..255 B granules (32 rows x 8)
            int r = gidx >> 3, o = gidx & 7;
            size_t go = (size_t)(k0 + r) * N + col_base + o * 8;
            cpa16(st + ST_BH + (uint32_t)(r * BST64 + o * 16), Wh + go);
        }
        cpa_commit();
    };
    load_chunk(0);
    for (int c = 0; c < NC; c++) {
        if (c + 1 < NC) { load_chunk(c + 1); cpa_wait<1>(); }
        else            { cpa_wait<0>(); }
        __syncthreads();
        const uint32_t st = sm + (uint32_t)((c & 1) * STAGE64_BYTES);
#pragma unroll
        for (int ks = 0; ks < 2; ks++) {
            uint32_t ah[2][4], bh[2][4];
#pragma unroll
            for (int mi = 0; mi < 2; mi++)
                ldsm_x4(ah[mi], st + ST_AH + a_lane +
                                (uint32_t)(mi * 16 * AST + ks * 32));
#pragma unroll
            for (int ni = 0; ni < 2; ni++)
                ldsm_x4t(bh[ni], st + ST_BH + b_lane +
                                 (uint32_t)(ks * 16 * BST64 + ni * 32));
#pragma unroll
            for (int ni = 0; ni < 2; ni++)
#pragma unroll
                for (int mi = 0; mi < 2; mi++) {
                    mma_f16(acc[mi][ni * 2 + 0], ah[mi], bh[ni][0], bh[ni][1]);
                    mma_f16(acc[mi][ni * 2 + 1], ah[mi], bh[ni][2], bh[ni][3]);
                }
        }
        __syncthreads();
    }

    const int g = lane >> 2;
    const int tg = lane & 3;
    float bv0[4], bv1[4];
#pragma unroll
    for (int nj = 0; nj < 4; nj++) {
        const int gcol = col_base + warp_n * 32 + nj * 8 + tg * 2;
        bv0[nj] = bias[gcol];
        bv1[nj] = bias[gcol + 1];
    }

#pragma unroll
    for (int mi = 0; mi < 2; mi++) {
        const int r0 = row_base + warp_m * 32 + mi * 16 + g;
        const int r1 = r0 + 8;
        float w0 = 0.0f, w1 = 0.0f;
        if (EPI == 2) { w0 = wmix[r0]; w1 = wmix[r1]; }
#pragma unroll
        for (int nj = 0; nj < 4; nj++) {
            const int gcol = col_base + warp_n * 32 + nj * 8 + tg * 2;
            float v00 = acc[mi][nj][0] + bv0[nj], v01 = acc[mi][nj][1] + bv1[nj];
            float v10 = acc[mi][nj][2] + bv0[nj], v11 = acc[mi][nj][3] + bv1[nj];
            if (EPI == 2) {
                float2 xo0 = *(const float2*)&xold[(size_t)r0 * N + gcol];
                float2 xo1 = *(const float2*)&xold[(size_t)r1 * N + gcol];
                v00 = w0 * v00 + (1.0f - w0) * xo0.x;
                v01 = w0 * v01 + (1.0f - w0) * xo0.y;
                v10 = w1 * v10 + (1.0f - w1) * xo1.x;
                v11 = w1 * v11 + (1.0f - w1) * xo1.y;
            }
            if (WF) {
                *(float2*)&Cf[(size_t)r0 * N + gcol] = make_float2(v00, v01);
                *(float2*)&Cf[(size_t)r1 * N + gcol] = make_float2(v10, v11);
            }
            if (WH) {
                *(__half2*)&Chh[(size_t)r0 * N + gcol] =
                    __halves2half2(__float2half_rn(v00), __float2half_rn(v01));
                *(__half2*)&Chh[(size_t)r1 * N + gcol] =
                    __halves2half2(__float2half_rn(v10), __float2half_rn(v11));
            }
        }
    }
}

// ---------------------------------------------------------------------------
// Router head GEMV + ACT state update (one warp per token)
// ---------------------------------------------------------------------------
__global__ void router_act_kernel(const float* __restrict__ rh,
                                  const float* __restrict__ Rw2i,
                                  const float* __restrict__ Rb2i)
{
    const int warp = threadIdx.x >> 5;
    const int lane = threadIdx.x & 31;
    const int t = blockIdx.x * 8 + warp;
    if (t >= M_) return;

    const float* r = rh + (size_t)t * HALF_;
    float s = 0.0f;
#pragma unroll
    for (int k = lane; k < HALF_; k += 32) s += r[k] * Rw2i[k];
#pragma unroll
    for (int o = 16; o > 0; o >>= 1) s += __shfl_xor_sync(0xffffffffu, s, o);

    if (lane == 0) {
        const float logit = s + Rb2i[0];
        const float p = 1.0f / (1.0f + expf(-logit));
        const float cum = g_cum[t];
        const float still = g_still[t];
        const float rem = fmaxf(1.0f - cum, 0.0f);
        const bool halt = (cum + p >= ACT_TAU);
        const float w = (halt ? rem : p) * still;
        g_w[t] = w;
        g_cum[t] = cum + w;
        g_wsum[t] += w;
        g_still[t] = halt ? 0.0f : still;
    }
}

__global__ void init_state_kernel()
{
    const int t = blockIdx.x * 256 + threadIdx.x;
    if (t < M_) {
        g_cum[t] = 0.0f;
        g_still[t] = 1.0f;
        g_wsum[t] = 1.0f;
    }
}

__global__ void budget_kernel(float* __restrict__ out)
{
    __shared__ float sh[256];
    float s = 0.0f;
    for (int t = threadIdx.x; t < M_; t += 256) s += g_wsum[t];
    sh[threadIdx.x] = s;
    __syncthreads();
#pragma unroll
    for (int o = 128; o > 0; o >>= 1) {
        if (threadIdx.x < o) sh[threadIdx.x] += sh[threadIdx.x + o];
        __syncthreads();
    }
    if (threadIdx.x == 0) {
        const float avg = sh[0] / (float)M_;
        const float d = avg - TARGET_DEPTH;
        const float rl = d > 0.0f ? d : 0.0f;
        out[0] = BUDGET_WEIGHT * rl * rl;
    }
}

// ---------------------------------------------------------------------------
// Launch
// ---------------------------------------------------------------------------
extern "C" void kernel_launch(void* const* d_in, const int* in_sizes, int n_in,
                              void* d_out, int out_size)
{
    const float* x_in = (const float*)d_in[0];
    const float* Wb1  = (const float*)d_in[1];
    const float* bb1  = (const float*)d_in[2];
    const float* Wb2  = (const float*)d_in[3];
    const float* bb2  = (const float*)d_in[4];
    const float* Rw1  = (const float*)d_in[5];  // (3, 1025, 512)
    const float* Rb1  = (const float*)d_in[6];  // (3, 512)
    const float* Rw2  = (const float*)d_in[7];  // (3, 512, 1)
    const float* Rb2  = (const float*)d_in[8];  // (3, 1)
    float* out = (float*)d_out;

    cudaFuncSetAttribute(g1_router,      cudaFuncAttributeMaxDynamicSharedMemorySize, SMEM_BYTES);
    cudaFuncSetAttribute(tgemm64<0,1,1>, cudaFuncAttributeMaxDynamicSharedMemorySize, SMEM64_BYTES);
    cudaFuncSetAttribute(tgemm64<2,1,1>, cudaFuncAttributeMaxDynamicSharedMemorySize, SMEM64_BYTES);
    cudaFuncSetAttribute(tgemm64<2,1,0>, cudaFuncAttributeMaxDynamicSharedMemorySize, SMEM64_BYTES);

    __half *W1h, *W2h, *R1h, *xh, *hh;
    float *gx, *grh, *gw;
    cudaGetSymbolAddress((void**)&W1h, g_W1h);
    cudaGetSymbolAddress((void**)&W2h, g_W2h);
    cudaGetSymbolAddress((void**)&R1h, g_R1h);
    cudaGetSymbolAddress((void**)&xh,  g_xh);
    cudaGetSymbolAddress((void**)&hh,  g_hh);
    cudaGetSymbolAddress((void**)&gx,  g_x);
    cudaGetSymbolAddress((void**)&grh, g_rh);
    cudaGetSymbolAddress((void**)&gw,  g_w);

    init_state_kernel<<<M_ / 256, 256>>>();

    // convert weights + input activations to fp16
    {
        int n4;
        n4 = H_ * DFF_ / 4;
        split_hi_kernel<<<(n4 + 255) / 256, 256>>>(Wb1, W1h, n4);
        split_hi_kernel<<<(n4 + 255) / 256, 256>>>(Wb2, W2h, n4);
        n4 = 3 * RW1_ROWS * HALF_ / 4;
        split_hi_kernel<<<(n4 + 255) / 256, 256>>>(Rw1, R1h, n4);
        n4 = M_ * H_ / 4;
        split_hi_kernel<<<(n4 + 255) / 256, 256>>>(x_in, xh, n4);
    }

    dim3 blk(NTHR);
    dim3 gr1(32, M_ / TBM);            // body GEMM1 alone (first pass)
    dim3 gr1r(36, M_ / TBM);           // body GEMM1 + fused router tiles
    dim3 gr2(H_ / 64, M_ / TBM);       // body GEMM2: 16 x 128 (64-wide tiles)

    // Mandatory first body pass: h = gelu(x W1 + b1); x = h W2 + b2
    g1_router<<<gr1, blk, SMEM_BYTES>>>(xh, W1h, bb1, hh, R1h, Rb1, grh);
    tgemm64<0,1,1><<<gr2, blk, SMEM64_BYTES>>>(hh, W2h, bb2, gx, xh,
                                               M_, H_, DFF_, nullptr, nullptr);

    for (int i = 0; i < 3; i++) {
        // Fused: h = gelu(x W1 + b1)  AND  rh = gelu(x Rw1_i + Rb1_i)
        const __half* R1hi = R1h + (size_t)i * RW1_ROWS * HALF_;
        g1_router<<<gr1r, blk, SMEM_BYTES>>>(xh, W1h, bb1, hh,
                                             R1hi, Rb1 + i * HALF_, grh);
        router_act_kernel<<<M_ / 8, 256>>>(grh, Rw2 + (size_t)i * HALF_, Rb2 + i);

        // Body GEMM2 + fused ACT soft mix
        if (i < 2) {
            tgemm64<2,1,1><<<gr2, blk, SMEM64_BYTES>>>(hh, W2h, bb2, gx, xh,
                                                       M_, H_, DFF_, gw, gx);
        } else {
            tgemm64<2,1,0><<<gr2, blk, SMEM64_BYTES>>>(hh, W2h, bb2, out, nullptr,
                                                       M_, H_, DFF_, gw, gx);
        }
    }

    if (out_size > (int)((size_t)M_ * H_))
        budget_kernel<<<1, 256>>>(out + (size_t)M_ * H_);
}

// round 17
// speedup vs baseline: 1.2699x; 1.2699x over previous
#include <cuda_runtime.h>
#include <cuda_fp16.h>
#include <math.h>
#include <stdint.h>

// ---------------------------------------------------------------------------
// Problem constants
// ---------------------------------------------------------------------------
#define B_ 4
#define T_ 2048
#define H_ 1024
#define DFF_ 4096
#define M_ (B_ * T_)      // 8192 tokens
#define HALF_ (H_ / 2)    // 512
#define ACT_TAU 0.99f
#define TARGET_DEPTH 2.5f
#define BUDGET_WEIGHT 0.01f
#define RW1_ROWS 1025

// ---------------------------------------------------------------------------
// Device scratch (no allocations allowed)
// ---------------------------------------------------------------------------
__device__ __align__(16) __half g_W1h[(size_t)H_ * DFF_];
__device__ __align__(16) __half g_W2h[(size_t)DFF_ * H_];
__device__ __align__(16) __half g_R1h[(size_t)3 * RW1_ROWS * HALF_];
__device__ __align__(16) __half g_xh[(size_t)M_ * H_];
__device__ __align__(16) __half g_hh[(size_t)M_ * DFF_];
__device__ float g_x[(size_t)M_ * H_];
__device__ float g_rh[(size_t)M_ * HALF_];
__device__ float g_w[M_];
__device__ float g_cum[M_];
__device__ float g_still[M_];
__device__ float g_wsum[M_];
__device__ int   g_idx0[M_];
__device__ int   g_idx1[M_];
__device__ int   g_cnt[2];

// ---------------------------------------------------------------------------
// Helpers
// ---------------------------------------------------------------------------
__device__ __forceinline__ uint32_t smem_u32(const void* p) {
    uint32_t a;
    asm("{ .reg .u64 t; cvta.to.shared.u64 t, %1; cvt.u32.u64 %0, t; }"
        : "=r"(a) : "l"(p));
    return a;
}

__device__ __forceinline__ float gelu_exact(float v) {
    return 0.5f * v * (1.0f + erff(v * 0.70710678118654752440f));
}

__device__ __forceinline__ void cpa16(uint32_t dst, const void* src) {
    asm volatile("cp.async.cg.shared.global [%0], [%1], 16;" :: "r"(dst), "l"(src));
}
__device__ __forceinline__ void cpa_commit() {
    asm volatile("cp.async.commit_group;" ::: "memory");
}
template <int N>
__device__ __forceinline__ void cpa_wait() {
    asm volatile("cp.async.wait_group %0;" :: "n"(N) : "memory");
}

__device__ __forceinline__ void ldsm_x4(uint32_t* r, uint32_t addr) {
    asm volatile("ldmatrix.sync.aligned.m8n8.x4.shared.b16 {%0,%1,%2,%3}, [%4];"
                 : "=r"(r[0]), "=r"(r[1]), "=r"(r[2]), "=r"(r[3]) : "r"(addr));
}
__device__ __forceinline__ void ldsm_x4t(uint32_t* r, uint32_t addr) {
    asm volatile("ldmatrix.sync.aligned.m8n8.x4.trans.shared.b16 {%0,%1,%2,%3}, [%4];"
                 : "=r"(r[0]), "=r"(r[1]), "=r"(r[2]), "=r"(r[3]) : "r"(addr));
}

// mma m16n8k16 fp16 -> fp32 accum
__device__ __forceinline__ void mma_f16(float* c, const uint32_t* a,
                                        uint32_t b0, uint32_t b1) {
    asm volatile(
        "mma.sync.aligned.m16n8k16.row.col.f32.f16.f16.f32 "
        "{%0,%1,%2,%3}, {%4,%5,%6,%7}, {%8,%9}, {%0,%1,%2,%3};"
        : "+f"(c[0]), "+f"(c[1]), "+f"(c[2]), "+f"(c[3])
        : "r"(a[0]), "r"(a[1]), "r"(a[2]), "r"(a[3]), "r"(b0), "r"(b1));
}

// ---------------------------------------------------------------------------
// fp32 -> fp16 convert ; fp32 copy
// ---------------------------------------------------------------------------
__global__ void split_hi_kernel(const float* __restrict__ src,
                                __half* __restrict__ hi, int n4)
{
    int i = blockIdx.x * 256 + threadIdx.x;
    if (i >= n4) return;
    float4 v = ((const float4*)src)[i];
    ((__half2*)hi)[i * 2 + 0] = __halves2half2(__float2half_rn(v.x), __float2half_rn(v.y));
    ((__half2*)hi)[i * 2 + 1] = __halves2half2(__float2half_rn(v.z), __float2half_rn(v.w));
}

__global__ void copy_kernel(const float* __restrict__ src, float* __restrict__ dst,
                            int n4)
{
    int i = blockIdx.x * 256 + threadIdx.x;
    if (i < n4) ((float4*)dst)[i] = ((const float4*)src)[i];
}

// ---------------------------------------------------------------------------
// Tile config: CTA 64x128, 128 threads (2x2 warps of 32x64), 5 CTAs/SM.
// ---------------------------------------------------------------------------
#define TBM 64
#define TBN 128
#define TBK 32
#define NTHR 128
#define AST 80       // A smem row stride bytes (32 fp16 = 64B + 16 pad)
#define BST 272      // B smem row stride bytes (128 fp16 = 256B + 16 pad)
#define A_BYTES (TBM * AST)                 // 5120
#define B_BYTES (32 * BST)                  // 8704
#define ST_AH 0
#define ST_BH A_BYTES
#define STAGE_BYTES (A_BYTES + B_BYTES)     // 13824
#define SMEM_BYTES (2 * STAGE_BYTES)        // 27648

// Mainloop: acc[2][8][4] = A_h * W_h. ROW(r) maps local A row -> global row.
#define GEMM_MAINLOOP(Ah_, Wh_, ldw_, K_, ROW)                                   \
    const int NC = (K_) / TBK;                                                   \
    auto load_chunk = [&](int c) {                                               \
        const uint32_t st = sm + (uint32_t)((c & 1) * STAGE_BYTES);              \
        const int k0 = c * TBK;                                                  \
        _Pragma("unroll")                                                        \
        for (int s = 0; s < 2; s++) {                                            \
            int gidx = tid + NTHR * s;       /* 0..255 A granules */             \
            int r = gidx >> 2, o = gidx & 3;                                     \
            size_t go = (size_t)(ROW(r)) * (K_) + k0 + o * 8;                    \
            cpa16(st + ST_AH + (uint32_t)(r * AST + o * 16), (Ah_) + go);        \
        }                                                                        \
        _Pragma("unroll")                                                        \
        for (int s = 0; s < 4; s++) {                                            \
            int gidx = tid + NTHR * s;       /* 0..511 B granules */             \
            int r = gidx >> 4, o = gidx & 15;                                    \
            size_t go = (size_t)(k0 + r) * (ldw_) + col_base + o * 8;            \
            cpa16(st + ST_BH + (uint32_t)(r * BST + o * 16), (Wh_) + go);        \
        }                                                                        \
        cpa_commit();                                                            \
    };                                                                           \
    load_chunk(0);                                                               \
    for (int c = 0; c < NC; c++) {                                               \
        if (c + 1 < NC) { load_chunk(c + 1); cpa_wait<1>(); }                    \
        else            { cpa_wait<0>(); }                                       \
        __syncthreads();                                                         \
        const uint32_t st = sm + (uint32_t)((c & 1) * STAGE_BYTES);              \
        _Pragma("unroll")                                                        \
        for (int ks = 0; ks < 2; ks++) {                                         \
            uint32_t ah[2][4], bh[4][4];                                         \
            _Pragma("unroll")                                                    \
            for (int mi = 0; mi < 2; mi++)                                       \
                ldsm_x4(ah[mi], st + ST_AH + a_lane +                            \
                                (uint32_t)(mi * 16 * AST + ks * 32));            \
            _Pragma("unroll")                                                    \
            for (int ni = 0; ni < 4; ni++)                                       \
                ldsm_x4t(bh[ni], st + ST_BH + b_lane +                           \
                                 (uint32_t)(ks * 16 * BST + ni * 32));           \
            _Pragma("unroll")                                                    \
            for (int ni = 0; ni < 4; ni++)                                       \
                _Pragma("unroll")                                                \
                for (int mi = 0; mi < 2; mi++) {                                 \
                    mma_f16(acc[mi][ni * 2 + 0], ah[mi], bh[ni][0], bh[ni][1]);  \
                    mma_f16(acc[mi][ni * 2 + 1], ah[mi], bh[ni][2], bh[ni][3]);  \
                }                                                                \
        }                                                                        \
        __syncthreads();                                                         \
    }

// ---------------------------------------------------------------------------
// Fused body-GEMM1 + router-GEMM kernel (gathered rows).
//   bx < 32 : h-tile  = gelu(x[tok]*W1 + bb1)      -> hh  (COMPACT rows, fp16)
//   bx >= 32: rh-tile = gelu(x[tok]*Rw1_i + Rb1_i) -> rh  (COMPACT rows, fp32)
// Rows beyond *cnt clamp to the last active token (benign duplicate compute).
// ---------------------------------------------------------------------------
__global__ __launch_bounds__(NTHR, 5)
void g1_router(const __half* __restrict__ Ah,
               const __half* __restrict__ W1, const float* __restrict__ b1,
               __half* __restrict__ Chh,
               const __half* __restrict__ Wr, const float* __restrict__ br,
               float* __restrict__ Crh,
               const int* __restrict__ idx, const int* __restrict__ cnt,
               int* __restrict__ next_cnt)
{
    extern __shared__ char smp[];
    __shared__ int sid[TBM];
    const uint32_t sm = smem_u32(smp);

    const int tid = threadIdx.x;
    if (blockIdx.x == 0 && blockIdx.y == 0 && tid == 0 && next_cnt) *next_cnt = 0;

    const int cntv = *cnt;
    const int row_base = blockIdx.y * TBM;
    if (row_base >= cntv) return;

    if (tid < TBM) {
        int cr = row_base + tid;
        sid[tid] = idx[cr < cntv ? cr : cntv - 1];
    }
    __syncthreads();

    const int lane = tid & 31;
    const int warp = tid >> 5;
    const int warp_m = warp & 1;
    const int warp_n = warp >> 1;

    const bool is_r = (blockIdx.x >= 32);
    const int col_base = (is_r ? (blockIdx.x - 32) : blockIdx.x) * TBN;
    const __half* Wh = is_r ? Wr : W1;
    const float* bias = is_r ? br : b1;
    const int ldw = is_r ? HALF_ : DFF_;

    float acc[2][8][4];
#pragma unroll
    for (int i = 0; i < 2; i++)
#pragma unroll
        for (int j = 0; j < 8; j++)
#pragma unroll
            for (int k = 0; k < 4; k++) acc[i][j][k] = 0.0f;

    const uint32_t a_lane = (uint32_t)((warp_m * 32 + (lane & 15)) * AST +
                                       (lane >> 4) * 16);
    const uint32_t b_lane = (uint32_t)((((lane >> 3) & 1) * 8 + (lane & 7)) * BST +
                                       (warp_n * 64 + (lane >> 4) * 8) * 2);

#define ROWMAP_G1(r) sid[r]
    GEMM_MAINLOOP(Ah, Wh, ldw, H_, ROWMAP_G1)
#undef ROWMAP_G1

    const int g = lane >> 2;
    const int tg = lane & 3;
    float bv0[8], bv1[8];
#pragma unroll
    for (int nj = 0; nj < 8; nj++) {
        const int gcol = col_base + warp_n * 64 + nj * 8 + tg * 2;
        bv0[nj] = bias[gcol];
        bv1[nj] = bias[gcol + 1];
    }

#pragma unroll
    for (int mi = 0; mi < 2; mi++) {
        const int lr0 = warp_m * 32 + mi * 16 + g;   // local compact row
        const int r0 = row_base + lr0;               // global compact row
        const int r1 = r0 + 8;
#pragma unroll
        for (int nj = 0; nj < 8; nj++) {
            const int gcol = col_base + warp_n * 64 + nj * 8 + tg * 2;
            float v00 = gelu_exact(acc[mi][nj][0] + bv0[nj]);
            float v01 = gelu_exact(acc[mi][nj][1] + bv1[nj]);
            float v10 = gelu_exact(acc[mi][nj][2] + bv0[nj]);
            float v11 = gelu_exact(acc[mi][nj][3] + bv1[nj]);
            if (is_r) {
                *(float2*)&Crh[(size_t)r0 * HALF_ + gcol] = make_float2(v00, v01);
                *(float2*)&Crh[(size_t)r1 * HALF_ + gcol] = make_float2(v10, v11);
            } else {
                *(__half2*)&Chh[(size_t)r0 * DFF_ + gcol] =
                    __halves2half2(__float2half_rn(v00), __float2half_rn(v01));
                *(__half2*)&Chh[(size_t)r1 * DFF_ + gcol] =
                    __halves2half2(__float2half_rn(v10), __float2half_rn(v11));
            }
        }
    }
}

// ---------------------------------------------------------------------------
// Body GEMM2: A = COMPACT hh rows; epilogue scatters by token id.
// EPI: 0=bias, 2=bias+ACT mix.  WF: write fp32 Cf[tok].  WH: write fp16 Chh[tok].
// ---------------------------------------------------------------------------
template <int EPI, int WF, int WH>
__global__ __launch_bounds__(NTHR, 5)
void tgemm(const __half* __restrict__ Ah, const __half* __restrict__ Wh,
           const float* __restrict__ bias, float* __restrict__ Cf,
           __half* __restrict__ Chh,
           int M, int N, int K,
           const float* __restrict__ wmix, const float* __restrict__ xold,
           const int* __restrict__ idx, const int* __restrict__ cnt)
{
    extern __shared__ char smp[];
    __shared__ int sid[TBM];
    const uint32_t sm = smem_u32(smp);

    const int tid = threadIdx.x;
    const int cntv = *cnt;
    const int row_base = blockIdx.y * TBM;
    if (row_base >= cntv) return;

    if (tid < TBM) {
        int cr = row_base + tid;
        sid[tid] = idx[cr < cntv ? cr : cntv - 1];
    }

    const int lane = tid & 31;
    const int warp = tid >> 5;
    const int warp_m = warp & 1;
    const int warp_n = warp >> 1;
    const int col_base = blockIdx.x * TBN;

    float acc[2][8][4];
#pragma unroll
    for (int i = 0; i < 2; i++)
#pragma unroll
        for (int j = 0; j < 8; j++)
#pragma unroll
            for (int k = 0; k < 4; k++) acc[i][j][k] = 0.0f;

    const uint32_t a_lane = (uint32_t)((warp_m * 32 + (lane & 15)) * AST +
                                       (lane >> 4) * 16);
    const uint32_t b_lane = (uint32_t)((((lane >> 3) & 1) * 8 + (lane & 7)) * BST +
                                       (warp_n * 64 + (lane >> 4) * 8) * 2);

#define ROWMAP_G2(r) (row_base + (r))
    GEMM_MAINLOOP(Ah, Wh, N, K, ROWMAP_G2)
#undef ROWMAP_G2

    const int g = lane >> 2;
    const int tg = lane & 3;
    float bv0[8], bv1[8];
#pragma unroll
    for (int nj = 0; nj < 8; nj++) {
        const int gcol = col_base + warp_n * 64 + nj * 8 + tg * 2;
        bv0[nj] = bias[gcol];
        bv1[nj] = bias[gcol + 1];
    }

#pragma unroll
    for (int mi = 0; mi < 2; mi++) {
        const int lr0 = warp_m * 32 + mi * 16 + g;
        const int t0 = sid[lr0];
        const int t1 = sid[lr0 + 8];
        float w0 = 0.0f, w1 = 0.0f;
        if (EPI == 2) { w0 = wmix[t0]; w1 = wmix[t1]; }
#pragma unroll
        for (int nj = 0; nj < 8; nj++) {
            const int gcol = col_base + warp_n * 64 + nj * 8 + tg * 2;
            float v00 = acc[mi][nj][0] + bv0[nj], v01 = acc[mi][nj][1] + bv1[nj];
            float v10 = acc[mi][nj][2] + bv0[nj], v11 = acc[mi][nj][3] + bv1[nj];
            if (EPI == 2) {
                float2 xo0 = *(const float2*)&xold[(size_t)t0 * N + gcol];
                float2 xo1 = *(const float2*)&xold[(size_t)t1 * N + gcol];
                v00 = w0 * v00 + (1.0f - w0) * xo0.x;
                v01 = w0 * v01 + (1.0f - w0) * xo0.y;
                v10 = w1 * v10 + (1.0f - w1) * xo1.x;
                v11 = w1 * v11 + (1.0f - w1) * xo1.y;
            }
            if (WF) {
                *(float2*)&Cf[(size_t)t0 * N + gcol] = make_float2(v00, v01);
                *(float2*)&Cf[(size_t)t1 * N + gcol] = make_float2(v10, v11);
            }
            if (WH) {
                *(__half2*)&Chh[(size_t)t0 * N + gcol] =
                    __halves2half2(__float2half_rn(v00), __float2half_rn(v01));
                *(__half2*)&Chh[(size_t)t1 * N + gcol] =
                    __halves2half2(__float2half_rn(v10), __float2half_rn(v11));
            }
        }
    }
}

// ---------------------------------------------------------------------------
// Router head GEMV + ACT state update (one warp per COMPACT row).
// Also builds the next iteration's active-token list.
// ---------------------------------------------------------------------------
__global__ void router_act_kernel(const float* __restrict__ rh,
                                  const float* __restrict__ Rw2i,
                                  const float* __restrict__ Rb2i,
                                  const int* __restrict__ idx,
                                  const int* __restrict__ cnt,
                                  int* __restrict__ next_idx,
                                  int* __restrict__ next_cnt)
{
    const int warp = threadIdx.x >> 5;
    const int lane = threadIdx.x & 31;
    const int cr = blockIdx.x * 8 + warp;
    const int cntv = *cnt;
    if (cr >= cntv) return;
    const int t = idx[cr];

    const float* r = rh + (size_t)cr * HALF_;
    float s = 0.0f;
#pragma unroll
    for (int k = lane; k < HALF_; k += 32) s += r[k] * Rw2i[k];
#pragma unroll
    for (int o = 16; o > 0; o >>= 1) s += __shfl_xor_sync(0xffffffffu, s, o);

    if (lane == 0) {
        const float logit = s + Rb2i[0];
        const float p = 1.0f / (1.0f + expf(-logit));
        const float cum = g_cum[t];
        const float still = g_still[t];
        const float rem = fmaxf(1.0f - cum, 0.0f);
        const bool halt = (cum + p >= ACT_TAU);
        const float w = (halt ? rem : p) * still;
        const float new_still = halt ? 0.0f : still;
        g_w[t] = w;
        g_cum[t] = cum + w;
        g_wsum[t] += w;
        g_still[t] = new_still;
        if (next_idx && new_still > 0.0f) {
            int pos = atomicAdd(next_cnt, 1);
            next_idx[pos] = t;
        }
    }
}

__global__ void init_state_kernel()
{
    const int t = blockIdx.x * 256 + threadIdx.x;
    if (t < M_) {
        g_cum[t] = 0.0f;
        g_still[t] = 1.0f;
        g_wsum[t] = 1.0f;
        g_idx0[t] = t;
    }
    if (t == 0) { g_cnt[0] = M_; g_cnt[1] = 0; }
}

__global__ void budget_kernel(float* __restrict__ out)
{
    __shared__ float sh[256];
    float s = 0.0f;
    for (int t = threadIdx.x; t < M_; t += 256) s += g_wsum[t];
    sh[threadIdx.x] = s;
    __syncthreads();
#pragma unroll
    for (int o = 128; o > 0; o >>= 1) {
        if (threadIdx.x < o) sh[threadIdx.x] += sh[threadIdx.x + o];
        __syncthreads();
    }
    if (threadIdx.x == 0) {
        const float avg = sh[0] / (float)M_;
        const float d = avg - TARGET_DEPTH;
        const float rl = d > 0.0f ? d : 0.0f;
        out[0] = BUDGET_WEIGHT * rl * rl;
    }
}

// ---------------------------------------------------------------------------
// Launch
// ---------------------------------------------------------------------------
extern "C" void kernel_launch(void* const* d_in, const int* in_sizes, int n_in,
                              void* d_out, int out_size)
{
    const float* x_in = (const float*)d_in[0];
    const float* Wb1  = (const float*)d_in[1];
    const float* bb1  = (const float*)d_in[2];
    const float* Wb2  = (const float*)d_in[3];
    const float* bb2  = (const float*)d_in[4];
    const float* Rw1  = (const float*)d_in[5];  // (3, 1025, 512)
    const float* Rb1  = (const float*)d_in[6];  // (3, 512)
    const float* Rw2  = (const float*)d_in[7];  // (3, 512, 1)
    const float* Rb2  = (const float*)d_in[8];  // (3, 1)
    float* out = (float*)d_out;

    cudaFuncSetAttribute(g1_router,    cudaFuncAttributeMaxDynamicSharedMemorySize, SMEM_BYTES);
    cudaFuncSetAttribute(tgemm<0,1,1>, cudaFuncAttributeMaxDynamicSharedMemorySize, SMEM_BYTES);
    cudaFuncSetAttribute(tgemm<2,1,1>, cudaFuncAttributeMaxDynamicSharedMemorySize, SMEM_BYTES);
    cudaFuncSetAttribute(tgemm<2,1,0>, cudaFuncAttributeMaxDynamicSharedMemorySize, SMEM_BYTES);

    __half *W1h, *W2h, *R1h, *xh, *hh;
    float *gx, *grh, *gw;
    int *idx0, *idx1, *cnt;
    cudaGetSymbolAddress((void**)&W1h, g_W1h);
    cudaGetSymbolAddress((void**)&W2h, g_W2h);
    cudaGetSymbolAddress((void**)&R1h, g_R1h);
    cudaGetSymbolAddress((void**)&xh,  g_xh);
    cudaGetSymbolAddress((void**)&hh,  g_hh);
    cudaGetSymbolAddress((void**)&gx,  g_x);
    cudaGetSymbolAddress((void**)&grh, g_rh);
    cudaGetSymbolAddress((void**)&gw,  g_w);
    cudaGetSymbolAddress((void**)&idx0, g_idx0);
    cudaGetSymbolAddress((void**)&idx1, g_idx1);
    cudaGetSymbolAddress((void**)&cnt,  g_cnt);

    init_state_kernel<<<M_ / 256, 256>>>();

    // convert weights + input activations to fp16
    {
        int n4;
        n4 = H_ * DFF_ / 4;
        split_hi_kernel<<<(n4 + 255) / 256, 256>>>(Wb1, W1h, n4);
        split_hi_kernel<<<(n4 + 255) / 256, 256>>>(Wb2, W2h, n4);
        n4 = 3 * RW1_ROWS * HALF_ / 4;
        split_hi_kernel<<<(n4 + 255) / 256, 256>>>(Rw1, R1h, n4);
        n4 = M_ * H_ / 4;
        split_hi_kernel<<<(n4 + 255) / 256, 256>>>(x_in, xh, n4);
    }

    dim3 blk(NTHR);
    dim3 gr1(32, M_ / TBM);            // body GEMM1 alone (first pass)
    dim3 gr1r(36, M_ / TBM);           // body GEMM1 + fused router tiles
    dim3 gr2(H_ / TBN, M_ / TBM);      // body GEMM2: 8 x 128

    int* idxs[2] = {idx0, idx1};

    // Mandatory first body pass (identity gather: idx0 = 0..M-1, cnt0 = M)
    g1_router<<<gr1, blk, SMEM_BYTES>>>(xh, W1h, bb1, hh, R1h, Rb1, grh,
                                        idx0, cnt + 0, nullptr);
    tgemm<0,1,1><<<gr2, blk, SMEM_BYTES>>>(hh, W2h, bb2, gx, xh,
                                           M_, H_, DFF_, nullptr, nullptr,
                                           idx0, cnt + 0);

    for (int i = 0; i < 3; i++) {
        const int cur = i & 1, nxt = (i + 1) & 1;
        const __half* R1hi = R1h + (size_t)i * RW1_ROWS * HALF_;

        // Fused gathered: h = gelu(x W1 + b1)  AND  rh = gelu(x Rw1_i + Rb1_i)
        // (also resets next iteration's count)
        g1_router<<<gr1r, blk, SMEM_BYTES>>>(xh, W1h, bb1, hh,
                                             R1hi, Rb1 + i * HALF_, grh,
                                             idxs[cur], cnt + cur, cnt + nxt);
        router_act_kernel<<<M_ / 8, 256>>>(grh, Rw2 + (size_t)i * HALF_, Rb2 + i,
                                           idxs[cur], cnt + cur,
                                           (i < 2) ? idxs[nxt] : nullptr,
                                           cnt + nxt);

        // Body GEMM2 + fused ACT soft mix (gathered)
        if (i < 2) {
            tgemm<2,1,1><<<gr2, blk, SMEM_BYTES>>>(hh, W2h, bb2, gx, xh,
                                                   M_, H_, DFF_, gw, gx,
                                                   idxs[cur], cnt + cur);
        } else {
            // inactive tokens keep x: pre-fill out with gx, then overwrite active
            copy_kernel<<<(M_ * H_ / 4 + 255) / 256, 256>>>(gx, out, M_ * H_ / 4);
            tgemm<2,1,0><<<gr2, blk, SMEM_BYTES>>>(hh, W2h, bb2, out, nullptr,
                                                   M_, H_, DFF_, gw, gx,
                                                   idxs[cur], cnt + cur);
        }
    }

    if (out_size > (int)((size_t)M_ * H_))
        budget_kernel<<<1, 256>>>(out + (size_t)M_ * H_);
}